// round 5
// baseline (speedup 1.0000x reference)
#include <cuda_runtime.h>
#include <math.h>

// FourierBlock: out = irfft2(modemix(rfft2(x))) + MLP(x) + Conv3x3(x)
// B=8, C=64, H=W=256, modes: kh in {0..31}u{224..255} (64), kw in {0..31}
// Packed fp32x2 (FFMA2) implementation.

typedef unsigned long long u64;
__device__ __forceinline__ u64 pk2(float lo, float hi) {
    u64 r; asm("mov.b64 %0,{%1,%2};" : "=l"(r) : "f"(lo), "f"(hi)); return r;
}
__device__ __forceinline__ u64 f2(u64 a, u64 b, u64 c) {
    u64 d; asm("fma.rn.f32x2 %0,%1,%2,%3;" : "=l"(d) : "l"(a), "l"(b), "l"(c)); return d;
}
__device__ __forceinline__ float2 up2(u64 v) {
    float2 r; asm("mov.b64 {%0,%1},%2;" : "=f"(r.x), "=f"(r.y) : "l"(v)); return r;
}

// ----------------------------- scratch ------------------------------------
__device__ __align__(16) float2 g_Y1[512*256*32];   // [bc][h][kw]
__device__ __align__(16) float2 g_Y2[512*64*32];    // [bc][khi][kw]
__device__ __align__(16) float2 g_Z [512*64*32];    // [bco][khi][kw]
__device__ __align__(16) float2 g_G [512*256*32];   // [bco][h][kw]
__device__ __align__(16) float2 g_TwA[256*32];      // [w][kw]  (cos,-sin)
__device__ __align__(16) float2 g_TwBp[256*64*2];   // [h][khi] pairs (c,-s),(s,c)
__device__ __align__(16) float2 g_TwCp[64*256*2];   // [khi][h] pairs (c,s),(-s,c)
__device__ __align__(16) float  g_Ct[32*256];       // [kw][w] coef*cos/65536
__device__ __align__(16) float  g_St[32*256];       // [kw][w] -coef*sin/65536
__device__ __align__(16) float2 g_Wp[2048*4096];    // [mode][ci*64+co]
__device__ __align__(16) float  g_Wc[64*9*64];      // [ci][tap][co]
__device__ __align__(16) float  g_W1t[64*128];      // [ci][hid]
__device__ __align__(16) float  g_W2t[128*64];      // [hid][co]

// ----------------------------- tables --------------------------------------
__global__ void k_tables() {
    int idx = blockIdx.x * 256 + threadIdx.x; // < 16384
    float s, c;
    if (idx < 256*32) { // TwA
        int w = idx >> 5, kw = idx & 31;
        sincospif((float)((w*kw)&255) * (1.0f/128.0f), &s, &c);
        g_TwA[idx] = make_float2(c, -s);
    }
    if (idx < 256*64) { // TwBp
        int h = idx >> 6, khi = idx & 63;
        int kh = (khi < 32) ? khi : khi + 192;
        sincospif((float)((h*kh)&255) * (1.0f/128.0f), &s, &c);
        g_TwBp[idx*2]   = make_float2(c, -s);
        g_TwBp[idx*2+1] = make_float2(s, c);
    }
    if (idx < 64*256) { // TwCp
        int khi = idx >> 8, h = idx & 255;
        int kh = (khi < 32) ? khi : khi + 192;
        sincospif((float)((h*kh)&255) * (1.0f/128.0f), &s, &c);
        g_TwCp[idx*2]   = make_float2(c, s);
        g_TwCp[idx*2+1] = make_float2(-s, c);
    }
    if (idx < 32*256) { // Ct/St
        int kw = idx >> 8, w = idx & 255;
        sincospif((float)((kw*w)&255) * (1.0f/128.0f), &s, &c);
        float coef = ((kw == 0) ? 1.0f : 2.0f) * (1.0f/65536.0f);
        g_Ct[idx] = coef * c;
        g_St[idx] = -coef * s;
    }
}

// ----------------------------- repacks -------------------------------------
__global__ void k_repack_wp(const float* __restrict__ w1r, const float* __restrict__ w1i,
                            const float* __restrict__ w2r, const float* __restrict__ w2i) {
    int idx = blockIdx.x * 256 + threadIdx.x;
    if (idx >= 2048*4096) return;
    int co  = idx & 63;
    int ci  = (idx >> 6) & 63;
    int kw  = (idx >> 12) & 31;
    int khi = idx >> 17;
    int kx  = (khi < 32) ? khi : khi - 32;
    int s   = ((ci*64 + co)*32 + kx)*32 + kw;
    g_Wp[idx] = (khi < 32) ? make_float2(w1r[s], w1i[s]) : make_float2(w2r[s], w2i[s]);
}

__global__ void k_repack_wc(const float* __restrict__ wc) {
    int idx = blockIdx.x * 256 + threadIdx.x;
    if (idx >= 64*9*64) return;
    int co = idx & 63, tap = (idx >> 6) % 9, ci = idx / 576;
    g_Wc[idx] = wc[(co*64 + ci)*9 + tap];
}

__global__ void k_repack_mlp(const float* __restrict__ w1, const float* __restrict__ w2) {
    int idx = blockIdx.x * 256 + threadIdx.x;
    if (idx < 8192) { // W1t[ci][hid] = w1[hid][ci]
        int ci = idx >> 7, hid = idx & 127;
        g_W1t[idx] = w1[hid*64 + ci];
    }
    if (idx < 8192) { // W2t[hid][co] = w2[co][hid]
        int hid = idx >> 6, co = idx & 63;
        g_W2t[idx] = w2[co*128 + hid];
    }
}

// ------------------ stage A: fwd DFT over W (32 bins) -----------------------
__global__ __launch_bounds__(256) void k_stageA(const float* __restrict__ x) {
    __shared__ float xs[32*256];
    int bc = blockIdx.x >> 3, hblk = blockIdx.x & 7;
    int t = threadIdx.x;
    for (int i = t; i < 8192; i += 256)
        xs[i] = x[(size_t)bc*65536 + (size_t)(hblk*32 + (i>>8))*256 + (i&255)];
    __syncthreads();
    int kw = t & 31, h0 = (t >> 5) * 4;
    u64 acc[4] = {0,0,0,0};
    const u64* tw = (const u64*)g_TwA;
    for (int w = 0; w < 256; w++) {
        u64 twv = tw[w*32 + kw];
        #pragma unroll
        for (int i = 0; i < 4; i++) {
            float xv = xs[(h0+i)*256 + w];
            acc[i] = f2(pk2(xv, xv), twv, acc[i]);
        }
    }
    u64* dst = (u64*)g_Y1;
    #pragma unroll
    for (int i = 0; i < 4; i++)
        dst[((size_t)bc*256 + hblk*32 + h0 + i)*32 + kw] = acc[i];
}

// ------------------ stage B: fwd DFT over H (64 bins) -----------------------
__global__ __launch_bounds__(256) void k_stageB() {
    __shared__ __align__(16) float2 ys[256*16];
    int bc = blockIdx.x >> 1, kh2 = blockIdx.x & 1;
    int t = threadIdx.x;
    for (int i = t; i < 4096; i += 256)
        ys[i] = g_Y1[(size_t)bc*8192 + (i>>4)*32 + kh2*16 + (i&15)];
    __syncthreads();
    int kwl = t & 15, khi0 = (t >> 4) * 4;
    u64 acc[4] = {0,0,0,0};
    const u64* tb = (const u64*)g_TwBp;
    for (int h = 0; h < 256; h++) {
        float2 y = ys[h*16 + kwl];
        u64 ya = pk2(y.x, y.x), yb = pk2(y.y, y.y);
        #pragma unroll
        for (int j = 0; j < 4; j++) {
            u64 p0 = tb[(h*64 + khi0 + j)*2];
            u64 p1 = tb[(h*64 + khi0 + j)*2 + 1];
            acc[j] = f2(ya, p0, acc[j]);
            acc[j] = f2(yb, p1, acc[j]);
        }
    }
    u64* dst = (u64*)g_Y2;
    #pragma unroll
    for (int j = 0; j < 4; j++)
        dst[(size_t)bc*2048 + (khi0+j)*32 + kh2*16 + kwl] = acc[j];
}

// ------------------ stage C: per-mode channel mix ---------------------------
__global__ __launch_bounds__(256) void k_stageC() {
    __shared__ __align__(16) u64 ya_s[512];     // [b][ci] splat re
    __shared__ __align__(16) u64 yb_s[512];     // [b][ci] splat im
    __shared__ __align__(16) float2 ws[4096];   // [ci][co]
    int mode = blockIdx.x, t = threadIdx.x;
    for (int i = t; i < 512; i += 256) {
        float2 y = g_Y2[(size_t)((i>>6)*64 + (i&63))*2048 + mode];
        ya_s[i] = pk2(y.x, y.x);
        yb_s[i] = pk2(y.y, y.y);
    }
    const float4* src = (const float4*)(g_Wp + (size_t)mode*4096);
    float4* dst4 = (float4*)ws;
    for (int i = t; i < 2048; i += 256) dst4[i] = src[i];
    __syncthreads();
    int co = t & 63, bg = t >> 6;
    u64 a1 = 0, a2 = 0;
    for (int ci = 0; ci < 64; ci++) {
        float2 w = ws[ci*64 + co];
        u64 p0 = pk2(w.x, w.y);
        u64 p1 = pk2(-w.y, w.x);
        a1 = f2(ya_s[bg*64 + ci], p0, a1);
        a1 = f2(yb_s[bg*64 + ci], p1, a1);
        a2 = f2(ya_s[(bg+4)*64 + ci], p0, a2);
        a2 = f2(yb_s[(bg+4)*64 + ci], p1, a2);
    }
    u64* z = (u64*)g_Z;
    z[(size_t)(bg*64 + co)*2048 + mode]     = a1;
    z[(size_t)((bg+4)*64 + co)*2048 + mode] = a2;
}

// ------------------ stage D: inv DFT over H ---------------------------------
__global__ __launch_bounds__(256) void k_stageD() {
    __shared__ __align__(16) float2 zs[64*32];
    int bco = blockIdx.x >> 3, hblk = blockIdx.x & 7;
    int t = threadIdx.x;
    for (int i = t; i < 2048; i += 256) zs[i] = g_Z[(size_t)bco*2048 + i];
    __syncthreads();
    int kw = t & 31, h0 = hblk*32 + (t >> 5)*4;
    u64 acc[4] = {0,0,0,0};
    const u64* tc = (const u64*)g_TwCp;
    for (int khi = 0; khi < 64; khi++) {
        float2 z = zs[khi*32 + kw];
        u64 za = pk2(z.x, z.x), zb = pk2(z.y, z.y);
        #pragma unroll
        for (int j = 0; j < 4; j++) {
            u64 p0 = tc[(khi*256 + h0 + j)*2];
            u64 p1 = tc[(khi*256 + h0 + j)*2 + 1];
            acc[j] = f2(za, p0, acc[j]);
            acc[j] = f2(zb, p1, acc[j]);
        }
    }
    u64* g = (u64*)g_G;
    #pragma unroll
    for (int j = 0; j < 4; j++)
        g[(size_t)bco*8192 + (h0+j)*32 + kw] = acc[j];
}

// ------------------ stage E: inv DFT over W + add to out --------------------
__global__ __launch_bounds__(256) void k_stageE(float* __restrict__ out) {
    __shared__ __align__(16) float2 gt[32*33];  // [kw][h] padded
    __shared__ __align__(16) float  Cs[2048];
    __shared__ __align__(16) float  Ss[2048];
    __shared__ __align__(16) float  st[32*66];  // [h][w] padded (even stride)
    int bco = blockIdx.x >> 5, hblk = (blockIdx.x >> 2) & 7, wblk = blockIdx.x & 3;
    int t = threadIdx.x;
    for (int i = t; i < 1024; i += 256) {
        int h = i >> 5, kw = i & 31;
        gt[kw*33 + h] = g_G[(size_t)bco*8192 + (hblk*32 + h)*32 + kw];
    }
    for (int i = t; i < 2048; i += 256) {
        int kw = i >> 6, wl = i & 63;
        Cs[i] = g_Ct[kw*256 + wblk*64 + wl];
        Ss[i] = g_St[kw*256 + wblk*64 + wl];
    }
    __syncthreads();
    int h = t & 31, wg = t >> 5;
    u64 acc[4] = {0,0,0,0};
    for (int kw = 0; kw < 32; kw++) {
        float2 g = gt[kw*33 + h];
        u64 ga = pk2(g.x, g.x), gb = pk2(g.y, g.y);
        const u64* c2 = (const u64*)(Cs + kw*64 + wg*8);
        const u64* s2 = (const u64*)(Ss + kw*64 + wg*8);
        #pragma unroll
        for (int p = 0; p < 4; p++) {
            acc[p] = f2(ga, c2[p], acc[p]);
            acc[p] = f2(gb, s2[p], acc[p]);
        }
    }
    #pragma unroll
    for (int p = 0; p < 4; p++) {
        float2 v = up2(acc[p]);
        st[h*66 + wg*8 + p*2]     = v.x;
        st[h*66 + wg*8 + p*2 + 1] = v.y;
    }
    __syncthreads();
    for (int i = t; i < 2048; i += 256) {
        int h2 = i >> 6, wl = i & 63;
        out[(size_t)bco*65536 + (size_t)(hblk*32 + h2)*256 + wblk*64 + wl] += st[h2*66 + wl];
    }
}

// ------------------ MLP: 64 -> 128 gelu -> 64 (writes out) ------------------
__global__ __launch_bounds__(256) void k_mlp(const float* __restrict__ x,
                                             const float* __restrict__ b1,
                                             const float* __restrict__ b2,
                                             float* __restrict__ out) {
    __shared__ __align__(16) float xs[4096];   // [ci][px]
    __shared__ __align__(16) float hs[8192];   // [hid][px]
    int b = blockIdx.x >> 10;
    int hw0 = (blockIdx.x & 1023) * 64;
    int t = threadIdx.x;
    for (int i = t; i < 4096; i += 256)
        xs[i] = x[(size_t)(b*64 + (i>>6))*65536 + hw0 + (i&63)];
    __syncthreads();
    // phase 1: 64 -> 128 + gelu
    {
        int px = t & 63, half = t >> 6;        // 4 halves x 32 hid
        u64 acc[16];
        const u64* bb = (const u64*)(b1 + half*32);
        #pragma unroll
        for (int j = 0; j < 16; j++) acc[j] = bb[j];
        const u64* wbase = (const u64*)(g_W1t + half*32);
        for (int ci = 0; ci < 64; ci++) {
            float xv = xs[ci*64 + px];
            u64 xp = pk2(xv, xv);
            const u64* w2 = wbase + ci*64;     // 64 u64 per ci row (128 floats)
            #pragma unroll
            for (int j = 0; j < 16; j++) acc[j] = f2(xp, w2[j], acc[j]);
        }
        #pragma unroll
        for (int j = 0; j < 16; j++) {
            float2 v = up2(acc[j]);
            float g0 = 0.5f * v.x * (1.0f + erff(v.x * 0.70710678118654752f));
            float g1 = 0.5f * v.y * (1.0f + erff(v.y * 0.70710678118654752f));
            hs[(half*32 + j*2)*64 + px]     = g0;
            hs[(half*32 + j*2 + 1)*64 + px] = g1;
        }
    }
    __syncthreads();
    // phase 2: 128 -> 64
    {
        int px = t & 63, cog = t >> 6;         // 4 groups x 16 co
        u64 acc[8];
        const u64* bb = (const u64*)(b2 + cog*16);
        #pragma unroll
        for (int j = 0; j < 8; j++) acc[j] = bb[j];
        const u64* wbase = (const u64*)(g_W2t + cog*16);
        for (int hid = 0; hid < 128; hid++) {
            float hv = hs[hid*64 + px];
            u64 hp = pk2(hv, hv);
            const u64* w2 = wbase + hid*32;    // 32 u64 per hid row (64 floats)
            #pragma unroll
            for (int j = 0; j < 8; j++) acc[j] = f2(hp, w2[j], acc[j]);
        }
        #pragma unroll
        for (int j = 0; j < 8; j++) {
            float2 v = up2(acc[j]);
            int co = cog*16 + j*2;
            out[(size_t)(b*64 + co)*65536 + hw0 + px]     = v.x;
            out[(size_t)(b*64 + co + 1)*65536 + hw0 + px] = v.y;
        }
    }
}

// ------------------ Conv3x3 (adds into out) ---------------------------------
__global__ __launch_bounds__(256) void k_conv(const float* __restrict__ x,
                                              const float* __restrict__ bconv,
                                              float* __restrict__ out) {
    __shared__ __align__(16) float xt[18*20];
    __shared__ __align__(16) float ws[576];
    int b = blockIdx.x >> 8;
    int tile = blockIdx.x & 255;
    int hbase = (tile >> 4) * 16, wbase = (tile & 15) * 16;
    int t = threadIdx.x;
    int py = t >> 4, px = t & 15;
    u64 acc[32];
    #pragma unroll
    for (int j = 0; j < 32; j++) acc[j] = 0;

    for (int ci = 0; ci < 64; ci++) {
        __syncthreads();
        for (int i = t; i < 324; i += 256) {
            int ih = i / 18, iw = i % 18;
            int gh = hbase + ih - 1, gw = wbase + iw - 1;
            float v = 0.0f;
            if (gh >= 0 && gh < 256 && gw >= 0 && gw < 256)
                v = x[(size_t)(b*64 + ci)*65536 + (size_t)gh*256 + gw];
            xt[ih*20 + iw] = v;
        }
        for (int i = t; i < 576; i += 256) ws[i] = g_Wc[ci*576 + i];
        __syncthreads();
        #pragma unroll
        for (int tap = 0; tap < 9; tap++) {
            float xv = xt[(tap/3 + py)*20 + px + tap%3];
            u64 xp = pk2(xv, xv);
            const u64* w2 = (const u64*)(ws + tap*64);
            #pragma unroll
            for (int j = 0; j < 32; j++) acc[j] = f2(xp, w2[j], acc[j]);
        }
    }
    size_t base = (size_t)b*4194304 + (size_t)(hbase + py)*256 + wbase + px;
    #pragma unroll
    for (int j = 0; j < 32; j++) {
        float2 v = up2(acc[j]);
        out[base + (size_t)(2*j)*65536]   += v.x + __ldg(&bconv[2*j]);
        out[base + (size_t)(2*j+1)*65536] += v.y + __ldg(&bconv[2*j+1]);
    }
}

// ------------------------------- launcher -----------------------------------
extern "C" void kernel_launch(void* const* d_in, const int* in_sizes, int n_in,
                              void* d_out, int out_size) {
    const float* x      = (const float*)d_in[0];
    const float* w1r    = (const float*)d_in[1];
    const float* w1i    = (const float*)d_in[2];
    const float* w2r    = (const float*)d_in[3];
    const float* w2i    = (const float*)d_in[4];
    const float* w_mlp1 = (const float*)d_in[5];
    const float* b_mlp1 = (const float*)d_in[6];
    const float* w_mlp2 = (const float*)d_in[7];
    const float* b_mlp2 = (const float*)d_in[8];
    const float* w_conv = (const float*)d_in[9];
    const float* b_conv = (const float*)d_in[10];
    float* out = (float*)d_out;

    k_tables<<<64, 256>>>();
    k_repack_wp<<<32768, 256>>>(w1r, w1i, w2r, w2i);
    k_repack_wc<<<144, 256>>>(w_conv);
    k_repack_mlp<<<32, 256>>>(w_mlp1, w_mlp2);

    k_stageA<<<4096, 256>>>(x);
    k_stageB<<<1024, 256>>>();
    k_stageC<<<2048, 256>>>();
    k_stageD<<<4096, 256>>>();

    k_mlp<<<8192, 256>>>(x, b_mlp1, b_mlp2, out);
    k_conv<<<2048, 256>>>(x, b_conv, out);
    k_stageE<<<16384, 256>>>(out);
}

// round 8
// speedup vs baseline: 2.0418x; 2.0418x over previous
#include <cuda_runtime.h>
#include <math.h>
#include <stdint.h>

// FourierBlock: out = irfft2(modemix(rfft2(x))) + MLP(x) + Conv3x3(x)
// B=8, C=64, H=W=256, modes: kh in {0..31}u{224..255} (64), kw in {0..31}
// Spectral path: scalar fp32 truncated-DFT GEMM stages (proven in R2).
// Conv3x3 + MLP: tf32 mma.sync tensor-core path (fp32 accumulate).

typedef unsigned int u32;

__device__ __forceinline__ u32 tf32u(float f) {
    u32 r; asm("cvt.rna.tf32.f32 %0,%1;" : "=r"(r) : "f"(f)); return r;
}
__device__ __forceinline__ float tf32f(float f) {
    return __uint_as_float(tf32u(f));
}
__device__ __forceinline__ void mma8(float& c0, float& c1, float& c2, float& c3,
                                     u32 a0, u32 a1, u32 a2, u32 a3, u32 b0, u32 b1) {
    asm("mma.sync.aligned.m16n8k8.row.col.f32.tf32.tf32.f32 "
        "{%0,%1,%2,%3},{%4,%5,%6,%7},{%8,%9},{%0,%1,%2,%3};"
        : "+f"(c0), "+f"(c1), "+f"(c2), "+f"(c3)
        : "r"(a0), "r"(a1), "r"(a2), "r"(a3), "r"(b0), "r"(b1));
}
__device__ __forceinline__ float gelu(float v) {
    return 0.5f * v * (1.0f + erff(v * 0.70710678118654752f));
}

// ----------------------------- scratch ------------------------------------
__device__ __align__(16) float2 g_Y1[512*256*32];   // [bc][h][kw]
__device__ __align__(16) float2 g_Y2[512*64*32];    // [bc][khi][kw]
__device__ __align__(16) float2 g_Z [512*64*32];    // [bco][khi][kw]
__device__ __align__(16) float2 g_G [512*256*32];   // [bco][h][kw]
__device__ __align__(16) float2 g_TwA[256*32];      // [w][kw]  (cos,-sin)
__device__ __align__(16) float2 g_TwB[256*64];      // [h][khi] (cos,-sin)
__device__ __align__(16) float2 g_TwC[64*256];      // [khi][h] (cos,+sin)
__device__ __align__(16) float  g_Ct[32*256];       // [kw][w] coef*cos/65536
__device__ __align__(16) float  g_St[32*256];       // [kw][w] -coef*sin/65536
__device__ __align__(16) float2 g_Wp[2048*4096];    // [mode][ci*64+co]
__device__ __align__(16) float  g_Wc2[9*64*64];     // [tap][ci][co] tf32
__device__ __align__(16) float  g_W1p[64*136];      // [ci][hid] pad136 tf32
__device__ __align__(16) float  g_W2p[128*72];      // [hid][co] pad72 tf32

// ----------------------------- tables --------------------------------------
__global__ void k_tables() {
    int idx = blockIdx.x * 256 + threadIdx.x; // < 16384
    float s, c;
    if (idx < 256*32) { // TwA
        int w = idx >> 5, kw = idx & 31;
        sincospif((float)((w*kw)&255) * (1.0f/128.0f), &s, &c);
        g_TwA[idx] = make_float2(c, -s);
    }
    if (idx < 256*64) { // TwB
        int h = idx >> 6, khi = idx & 63;
        int kh = (khi < 32) ? khi : khi + 192;
        sincospif((float)((h*kh)&255) * (1.0f/128.0f), &s, &c);
        g_TwB[idx] = make_float2(c, -s);
    }
    if (idx < 64*256) { // TwC
        int khi = idx >> 8, h = idx & 255;
        int kh = (khi < 32) ? khi : khi + 192;
        sincospif((float)((h*kh)&255) * (1.0f/128.0f), &s, &c);
        g_TwC[idx] = make_float2(c, s);
    }
    if (idx < 32*256) { // Ct/St
        int kw = idx >> 8, w = idx & 255;
        sincospif((float)((kw*w)&255) * (1.0f/128.0f), &s, &c);
        float coef = ((kw == 0) ? 1.0f : 2.0f) * (1.0f/65536.0f);
        g_Ct[idx] = coef * c;
        g_St[idx] = -coef * s;
    }
}

// ----------------------------- repacks -------------------------------------
__global__ void k_repack_wp(const float* __restrict__ w1r, const float* __restrict__ w1i,
                            const float* __restrict__ w2r, const float* __restrict__ w2i) {
    int idx = blockIdx.x * 256 + threadIdx.x;
    if (idx >= 2048*4096) return;
    int co  = idx & 63;
    int ci  = (idx >> 6) & 63;
    int kw  = (idx >> 12) & 31;
    int khi = idx >> 17;
    int kx  = (khi < 32) ? khi : khi - 32;
    int s   = ((ci*64 + co)*32 + kx)*32 + kw;
    g_Wp[idx] = (khi < 32) ? make_float2(w1r[s], w1i[s]) : make_float2(w2r[s], w2i[s]);
}

__global__ void k_repack_tc(const float* __restrict__ wconv,
                            const float* __restrict__ w1,
                            const float* __restrict__ w2) {
    int idx = blockIdx.x * 256 + threadIdx.x;   // grid covers 36864
    if (idx < 9*64*64) {
        int co = idx & 63, ci = (idx >> 6) & 63, tap = idx >> 12;
        g_Wc2[tap*4096 + ci*64 + co] = tf32f(wconv[(co*64 + ci)*9 + tap]);
    }
    if (idx < 64*128) {
        int hid = idx & 127, ci = idx >> 7;
        g_W1p[ci*136 + hid] = tf32f(w1[hid*64 + ci]);
    }
    if (idx < 128*64) {
        int co = idx & 63, hid = idx >> 6;
        g_W2p[hid*72 + co] = tf32f(w2[co*128 + hid]);
    }
}

// ------------------ stage A: fwd DFT over W (32 bins) -----------------------
__global__ __launch_bounds__(256) void k_stageA(const float* __restrict__ x) {
    __shared__ float xs[32*256];
    int bc = blockIdx.x >> 3, hblk = blockIdx.x & 7;
    int t = threadIdx.x;
    for (int i = t; i < 8192; i += 256)
        xs[i] = x[(size_t)bc*65536 + (size_t)(hblk*32 + (i>>8))*256 + (i&255)];
    __syncthreads();
    int kw = t & 31, h0 = (t >> 5) * 4;
    float ar[4] = {0,0,0,0}, ai[4] = {0,0,0,0};
    for (int w = 0; w < 256; w++) {
        float2 tw = g_TwA[w*32 + kw];
        #pragma unroll
        for (int i = 0; i < 4; i++) {
            float xv = xs[(h0+i)*256 + w];
            ar[i] += xv * tw.x;
            ai[i] += xv * tw.y;
        }
    }
    #pragma unroll
    for (int i = 0; i < 4; i++)
        g_Y1[((size_t)bc*256 + hblk*32 + h0 + i)*32 + kw] = make_float2(ar[i], ai[i]);
}

// ------------------ stage B: fwd DFT over H (64 bins) -----------------------
__global__ __launch_bounds__(256) void k_stageB() {
    __shared__ __align__(16) float2 ys[256*16];
    int bc = blockIdx.x >> 1, kh2 = blockIdx.x & 1;
    int t = threadIdx.x;
    for (int i = t; i < 4096; i += 256)
        ys[i] = g_Y1[(size_t)bc*8192 + (i>>4)*32 + kh2*16 + (i&15)];
    __syncthreads();
    int kwl = t & 15, khi0 = (t >> 4) * 4;
    float yr[4] = {0,0,0,0}, yi[4] = {0,0,0,0};
    for (int h = 0; h < 256; h++) {
        float2 y = ys[h*16 + kwl];
        const float4* tb = (const float4*)(g_TwB + h*64 + khi0);
        float4 t0 = tb[0], t1 = tb[1];
        yr[0] += y.x*t0.x - y.y*t0.y;  yi[0] += y.x*t0.y + y.y*t0.x;
        yr[1] += y.x*t0.z - y.y*t0.w;  yi[1] += y.x*t0.w + y.y*t0.z;
        yr[2] += y.x*t1.x - y.y*t1.y;  yi[2] += y.x*t1.y + y.y*t1.x;
        yr[3] += y.x*t1.z - y.y*t1.w;  yi[3] += y.x*t1.w + y.y*t1.z;
    }
    #pragma unroll
    for (int j = 0; j < 4; j++)
        g_Y2[(size_t)bc*2048 + (khi0+j)*32 + kh2*16 + kwl] = make_float2(yr[j], yi[j]);
}

// ------------------ stage C: per-mode channel mix ---------------------------
__global__ __launch_bounds__(256) void k_stageC() {
    __shared__ __align__(16) float2 ysm[512];   // [b][ci]
    __shared__ __align__(16) float2 ws[4096];   // [ci][co]
    int mode = blockIdx.x, t = threadIdx.x;
    for (int i = t; i < 512; i += 256) {
        int b = i >> 6, ci = i & 63;
        ysm[i] = g_Y2[(size_t)(b*64 + ci)*2048 + mode];
    }
    const float4* src = (const float4*)(g_Wp + (size_t)mode*4096);
    float4* dst4 = (float4*)ws;
    for (int i = t; i < 2048; i += 256) dst4[i] = src[i];
    __syncthreads();
    int co = t & 63, bg = t >> 6;
    float ar = 0, ai = 0, br = 0, bi = 0;
    for (int ci = 0; ci < 64; ci++) {
        float2 w = ws[ci*64 + co];
        float2 ya = ysm[bg*64 + ci];
        float2 yb = ysm[(bg+4)*64 + ci];
        ar += ya.x*w.x - ya.y*w.y;  ai += ya.x*w.y + ya.y*w.x;
        br += yb.x*w.x - yb.y*w.y;  bi += yb.x*w.y + yb.y*w.x;
    }
    g_Z[(size_t)(bg*64 + co)*2048 + mode]     = make_float2(ar, ai);
    g_Z[(size_t)((bg+4)*64 + co)*2048 + mode] = make_float2(br, bi);
}

// ------------------ stage D: inv DFT over H ---------------------------------
__global__ __launch_bounds__(256) void k_stageD() {
    __shared__ __align__(16) float2 zs[64*32];
    int bco = blockIdx.x >> 3, hblk = blockIdx.x & 7;
    int t = threadIdx.x;
    for (int i = t; i < 2048; i += 256) zs[i] = g_Z[(size_t)bco*2048 + i];
    __syncthreads();
    int kw = t & 31, h0 = hblk*32 + (t >> 5)*4;
    float gr[4] = {0,0,0,0}, gi[4] = {0,0,0,0};
    for (int khi = 0; khi < 64; khi++) {
        float2 z = zs[khi*32 + kw];
        const float4* tc = (const float4*)(g_TwC + khi*256 + h0);
        float4 t0 = tc[0], t1 = tc[1];
        gr[0] += z.x*t0.x - z.y*t0.y;  gi[0] += z.x*t0.y + z.y*t0.x;
        gr[1] += z.x*t0.z - z.y*t0.w;  gi[1] += z.x*t0.w + z.y*t0.z;
        gr[2] += z.x*t1.x - z.y*t1.y;  gi[2] += z.x*t1.y + z.y*t1.x;
        gr[3] += z.x*t1.z - z.y*t1.w;  gi[3] += z.x*t1.w + z.y*t1.z;
    }
    #pragma unroll
    for (int i = 0; i < 4; i++)
        g_G[(size_t)bco*8192 + (h0+i)*32 + kw] = make_float2(gr[i], gi[i]);
}

// ------------------ stage E: inv DFT over W + add to out --------------------
__global__ __launch_bounds__(256) void k_stageE(float* __restrict__ out) {
    __shared__ __align__(16) float2 gt[32*33];  // [kw][h] padded
    __shared__ __align__(16) float  Cs[2048];
    __shared__ __align__(16) float  Ss[2048];
    __shared__ __align__(16) float  st[32*65];  // [h][w] padded
    int bco = blockIdx.x >> 5, hblk = (blockIdx.x >> 2) & 7, wblk = blockIdx.x & 3;
    int t = threadIdx.x;
    for (int i = t; i < 1024; i += 256) {
        int h = i >> 5, kw = i & 31;
        gt[kw*33 + h] = g_G[(size_t)bco*8192 + (hblk*32 + h)*32 + kw];
    }
    for (int i = t; i < 2048; i += 256) {
        int kw = i >> 6, wl = i & 63;
        Cs[i] = g_Ct[kw*256 + wblk*64 + wl];
        Ss[i] = g_St[kw*256 + wblk*64 + wl];
    }
    __syncthreads();
    int h = t & 31, wg = t >> 5;
    float acc[8] = {0,0,0,0,0,0,0,0};
    for (int kw = 0; kw < 32; kw++) {
        float2 g = gt[kw*33 + h];
        const float4* c4 = (const float4*)(Cs + kw*64 + wg*8);
        const float4* s4 = (const float4*)(Ss + kw*64 + wg*8);
        float4 c0 = c4[0], c1 = c4[1], s0 = s4[0], s1 = s4[1];
        acc[0] += g.x*c0.x + g.y*s0.x;  acc[1] += g.x*c0.y + g.y*s0.y;
        acc[2] += g.x*c0.z + g.y*s0.z;  acc[3] += g.x*c0.w + g.y*s0.w;
        acc[4] += g.x*c1.x + g.y*s1.x;  acc[5] += g.x*c1.y + g.y*s1.y;
        acc[6] += g.x*c1.z + g.y*s1.z;  acc[7] += g.x*c1.w + g.y*s1.w;
    }
    #pragma unroll
    for (int j = 0; j < 8; j++) st[h*65 + wg*8 + j] = acc[j];
    __syncthreads();
    for (int i = t; i < 2048; i += 256) {
        int h2 = i >> 6, wl = i & 63;
        out[(size_t)bco*65536 + (size_t)(hblk*32 + h2)*256 + wblk*64 + wl] += st[h2*65 + wl];
    }
}

// ------------------ MLP via tf32 mma (writes out) ---------------------------
// CTA: 64 pixels x full channels. smem floats:
//   hs  [128][72] at 0      (36864 B)
//   xs  [64][72]  at 9216   (18432 B)   phase1 only
//   ws1 [64][136] at 13824  (34816 B)   phase1 only
//   ws2 [128][72] at 9216   (36864 B)   phase2, overlays xs/ws1
#define MLP_SMEM ((128*72 + 64*72 + 64*136) * 4)
__global__ __launch_bounds__(256) void k_mlp(const float* __restrict__ x,
                                             const float* __restrict__ b1,
                                             const float* __restrict__ b2,
                                             float* __restrict__ out) {
    extern __shared__ float sm[];
    float* hs  = sm;
    float* xs  = sm + 9216;
    float* ws1 = sm + 13824;
    float* ws2 = sm + 9216;
    int b = blockIdx.x >> 10;
    int hw0 = (blockIdx.x & 1023) * 64;
    int t = threadIdx.x, wid = t >> 5, lane = t & 31;
    int g = lane >> 2, tig = lane & 3;
    int mt = wid & 3, nh = wid >> 2;

    for (int i = t; i < 4096; i += 256)
        xs[(i>>6)*72 + (i&63)] = x[(size_t)(b*64 + (i>>6))*65536 + hw0 + (i&63)];
    for (int i = t; i < 8704; i += 256) ws1[i] = g_W1p[i];
    __syncthreads();

    // phase 1: [64px x 64ci] x [64ci x 128hid], warp: 16 px (mt), 64 hid (nh)
    {
        float c[8][4];
        #pragma unroll
        for (int nt = 0; nt < 8; nt++) {
            int hid0 = nh*64 + nt*8 + 2*tig;
            float v0 = __ldg(&b1[hid0]);
            float v1 = __ldg(&b1[hid0+1]);
            c[nt][0] = v0; c[nt][1] = v1; c[nt][2] = v0; c[nt][3] = v1;
        }
        #pragma unroll
        for (int kt = 0; kt < 8; kt++) {
            int ci = kt*8 + tig;
            u32 a0 = tf32u(xs[ci*72 + mt*16 + g]);
            u32 a1 = tf32u(xs[ci*72 + mt*16 + g + 8]);
            u32 a2 = tf32u(xs[(ci+4)*72 + mt*16 + g]);
            u32 a3 = tf32u(xs[(ci+4)*72 + mt*16 + g + 8]);
            #pragma unroll
            for (int nt = 0; nt < 8; nt++) {
                u32 b0 = __float_as_uint(ws1[ci*136 + nh*64 + nt*8 + g]);
                u32 bb = __float_as_uint(ws1[(ci+4)*136 + nh*64 + nt*8 + g]);
                mma8(c[nt][0], c[nt][1], c[nt][2], c[nt][3], a0, a1, a2, a3, b0, bb);
            }
        }
        #pragma unroll
        for (int nt = 0; nt < 8; nt++) {
            int hid0 = nh*64 + nt*8 + 2*tig;
            int px = mt*16 + g;
            hs[hid0*72 + px]         = gelu(c[nt][0]);
            hs[(hid0+1)*72 + px]     = gelu(c[nt][1]);
            hs[hid0*72 + px + 8]     = gelu(c[nt][2]);
            hs[(hid0+1)*72 + px + 8] = gelu(c[nt][3]);
        }
    }
    __syncthreads();
    for (int i = t; i < 9216; i += 256) ws2[i] = g_W2p[i];
    __syncthreads();

    // phase 2: [64px x 128hid] x [128hid x 64co], warp: 16 px (mt), 32 co (nh)
    {
        float c[4][4];
        #pragma unroll
        for (int nt = 0; nt < 4; nt++) {
            int co0 = nh*32 + nt*8 + 2*tig;
            float v0 = __ldg(&b2[co0]);
            float v1 = __ldg(&b2[co0+1]);
            c[nt][0] = v0; c[nt][1] = v1; c[nt][2] = v0; c[nt][3] = v1;
        }
        #pragma unroll
        for (int kt = 0; kt < 16; kt++) {
            int hid = kt*8 + tig;
            u32 a0 = tf32u(hs[hid*72 + mt*16 + g]);
            u32 a1 = tf32u(hs[hid*72 + mt*16 + g + 8]);
            u32 a2 = tf32u(hs[(hid+4)*72 + mt*16 + g]);
            u32 a3 = tf32u(hs[(hid+4)*72 + mt*16 + g + 8]);
            #pragma unroll
            for (int nt = 0; nt < 4; nt++) {
                u32 b0 = __float_as_uint(ws2[hid*72 + nh*32 + nt*8 + g]);
                u32 bb = __float_as_uint(ws2[(hid+4)*72 + nh*32 + nt*8 + g]);
                mma8(c[nt][0], c[nt][1], c[nt][2], c[nt][3], a0, a1, a2, a3, b0, bb);
            }
        }
        size_t obase = (size_t)(b*64)*65536 + hw0 + mt*16 + g;
        #pragma unroll
        for (int nt = 0; nt < 4; nt++) {
            int co0 = nh*32 + nt*8 + 2*tig;
            out[obase + (size_t)co0*65536]         = c[nt][0];
            out[obase + (size_t)(co0+1)*65536]     = c[nt][1];
            out[obase + (size_t)co0*65536 + 8]     = c[nt][2];
            out[obase + (size_t)(co0+1)*65536 + 8] = c[nt][3];
        }
    }
}

// ------------------ Conv3x3 via tf32 mma (adds into out) --------------------
// CTA tile: 8h x 16w pixels x 64 co. smem floats:
//   xt [64][184] (10x18 region per ci)  at 0       (47104 B)
//   ws [2][64*72]                        at 11776   (36864 B)
#define CV_SMEM ((64*184 + 2*64*72) * 4)
__global__ __launch_bounds__(256) void k_conv(const float* __restrict__ x,
                                              const float* __restrict__ bconv,
                                              float* __restrict__ out) {
    extern __shared__ float sm[];
    float* xt = sm;
    float* ws = sm + 64*184;
    int b = blockIdx.x >> 9;
    int tile = blockIdx.x & 511;
    int hbase = (tile >> 4) * 8, wbase = (tile & 15) * 16;
    int t = threadIdx.x, wid = t >> 5, lane = t & 31;
    int g = lane >> 2, tig = lane & 3;

    for (int i = t; i < 64*180; i += 256) {
        int ci = i / 180, r = i % 180;
        int iy = r / 18, ix = r - iy*18;
        int gh = hbase + iy - 1, gw = wbase + ix - 1;
        float v = 0.0f;
        if (gh >= 0 && gh < 256 && gw >= 0 && gw < 256)
            v = x[(size_t)(b*64 + ci)*65536 + (size_t)gh*256 + gw];
        xt[ci*184 + iy*18 + ix] = v;
    }
    for (int i = t; i < 4096; i += 256)
        ws[(i>>6)*72 + (i&63)] = g_Wc2[i];

    float c[8][4];
    #pragma unroll
    for (int nt = 0; nt < 8; nt++) {
        int co0 = nt*8 + 2*tig;
        float v0 = __ldg(&bconv[co0]);
        float v1 = __ldg(&bconv[co0+1]);
        c[nt][0] = v0; c[nt][1] = v1; c[nt][2] = v0; c[nt][3] = v1;
    }

    for (int tap = 0; tap < 9; tap++) {
        __syncthreads();
        float* wcur = ws + (tap & 1) * 4608;
        if (tap < 8) {
            float* wnext = ws + ((tap+1) & 1) * 4608;
            const float* src = g_Wc2 + (tap+1)*4096;
            for (int i = t; i < 4096; i += 256)
                wnext[(i>>6)*72 + (i&63)] = src[i];
        }
        int dy = tap / 3, dx = tap - dy*3;
        int abase = (wid + dy)*18 + dx;
        #pragma unroll
        for (int kt = 0; kt < 8; kt++) {
            int ci = kt*8 + tig;
            u32 a0 = tf32u(xt[ci*184 + abase + g]);
            u32 a1 = tf32u(xt[ci*184 + abase + g + 8]);
            u32 a2 = tf32u(xt[(ci+4)*184 + abase + g]);
            u32 a3 = tf32u(xt[(ci+4)*184 + abase + g + 8]);
            #pragma unroll
            for (int nt = 0; nt < 8; nt++) {
                u32 b0 = __float_as_uint(wcur[ci*72 + nt*8 + g]);
                u32 bb = __float_as_uint(wcur[(ci+4)*72 + nt*8 + g]);
                mma8(c[nt][0], c[nt][1], c[nt][2], c[nt][3], a0, a1, a2, a3, b0, bb);
            }
        }
    }
    size_t obase = (size_t)(b*64)*65536 + (size_t)(hbase + wid)*256 + wbase + g;
    #pragma unroll
    for (int nt = 0; nt < 8; nt++) {
        int co0 = nt*8 + 2*tig;
        out[obase + (size_t)co0*65536]         += c[nt][0];
        out[obase + (size_t)(co0+1)*65536]     += c[nt][1];
        out[obase + (size_t)co0*65536 + 8]     += c[nt][2];
        out[obase + (size_t)(co0+1)*65536 + 8] += c[nt][3];
    }
}

// ------------------------------- launcher -----------------------------------
extern "C" void kernel_launch(void* const* d_in, const int* in_sizes, int n_in,
                              void* d_out, int out_size) {
    const float* x      = (const float*)d_in[0];
    const float* w1r    = (const float*)d_in[1];
    const float* w1i    = (const float*)d_in[2];
    const float* w2r    = (const float*)d_in[3];
    const float* w2i    = (const float*)d_in[4];
    const float* w_mlp1 = (const float*)d_in[5];
    const float* b_mlp1 = (const float*)d_in[6];
    const float* w_mlp2 = (const float*)d_in[7];
    const float* b_mlp2 = (const float*)d_in[8];
    const float* w_conv = (const float*)d_in[9];
    const float* b_conv = (const float*)d_in[10];
    float* out = (float*)d_out;

    cudaFuncSetAttribute(k_mlp,  cudaFuncAttributeMaxDynamicSharedMemorySize, MLP_SMEM);
    cudaFuncSetAttribute(k_conv, cudaFuncAttributeMaxDynamicSharedMemorySize, CV_SMEM);

    k_tables<<<64, 256>>>();
    k_repack_wp<<<32768, 256>>>(w1r, w1i, w2r, w2i);
    k_repack_tc<<<144, 256>>>(w_conv, w_mlp1, w_mlp2);

    k_stageA<<<4096, 256>>>(x);
    k_stageB<<<1024, 256>>>();
    k_stageC<<<2048, 256>>>();
    k_stageD<<<4096, 256>>>();

    k_mlp<<<8192, 256, MLP_SMEM>>>(x, b_mlp1, b_mlp2, out);
    k_conv<<<4096, 256, CV_SMEM>>>(x, b_conv, out);
    k_stageE<<<16384, 256>>>(out);
}